// round 4
// baseline (speedup 1.0000x reference)
#include <cuda_runtime.h>

#define NN 100000
#define EE 1600000
#define FH 32
#define SCAN_THREADS 1024
#define BINS_PER_THREAD 98   // 1024*98 = 100352 >= NN

// ---------------- device scratch (static; no allocations) ----------------
__device__ int g_idx64;                          // 1 if edge_index is int64
__device__ __align__(16) int   g_src[EE];
__device__ __align__(16) int   g_dst[EE];
__device__ __align__(16) unsigned long long g_edges[EE];  // packed {src(lo32), nw bits(hi32)}, bucketed by dst
__device__ __align__(16) float g_deg[NN];        // weighted out-degree, then dinv
__device__ __align__(16) int   g_cnt[NN];        // in-degree histogram
__device__ __align__(16) int   g_off[NN + 1];    // CSR offsets (by dst)
__device__ __align__(16) int   g_cursor[NN];     // bucket fill cursors
__device__ __align__(16) float g_aggx[NN * FH];  // agg(nw*x[src]) (stored by gate, reused by out)
__device__ __align__(16) float g_Z[NN * FH];
__device__ __align__(16) float g_HR[NN * FH];

// ---------------- kernels ----------------

// Probe edge_index dtype: true int64 indices are all < NN; int32 data read as
// u64 is >= 2^32 unless the odd word happens to be zero (~1e-5 per entry).
__global__ void detect_kernel(const void* ei) {
    const unsigned long long* p = (const unsigned long long*)ei;
    int is64 = 1;
    for (int i = 0; i < 16; i++)
        if (p[i] >= (unsigned long long)NN) is64 = 0;
    g_idx64 = is64;
}

__global__ void zero_kernel() {
    int i = blockIdx.x * blockDim.x + threadIdx.x;
    if (i < NN) {
        g_deg[i] = 0.f;
        g_cnt[i] = 0;
    }
}

// Pass A: convert indices, weighted out-degree (by src), in-degree histogram (by dst).
__global__ void passA_kernel(const void* ei, const float* __restrict__ ew) {
    int e = blockIdx.x * blockDim.x + threadIdx.x;
    if (e >= EE) return;
    int s, d;
    if (g_idx64) {
        const long long* p = (const long long*)ei;
        s = (int)p[e];
        d = (int)p[EE + e];
    } else {
        const int* p = (const int*)ei;
        s = p[e];
        d = p[EE + e];
    }
    g_src[e] = s;
    g_dst[e] = d;
    float w = (s == d) ? 0.f : ew[e];
    if (w != 0.f) atomicAdd(&g_deg[s], w);
    atomicAdd(&g_cnt[d], 1);
}

__global__ void dinv_kernel() {
    int i = blockIdx.x * blockDim.x + threadIdx.x;
    if (i >= NN) return;
    float dg = g_deg[i];
    g_deg[i] = (dg > 0.f) ? rsqrtf(fmaxf(dg, 1e-30f)) : 0.f;
}

// Single-block exclusive scan of g_cnt -> g_off (+ cursor copy, + g_off[NN]).
__global__ void __launch_bounds__(SCAN_THREADS) scan_kernel() {
    __shared__ int partial[SCAN_THREADS];
    int t = threadIdx.x;
    int begin = t * BINS_PER_THREAD;
    int end = min(begin + BINS_PER_THREAD, NN);
    int sum = 0;
    for (int i = begin; i < end; i++) sum += g_cnt[i];
    partial[t] = sum;
    __syncthreads();
    // Hillis-Steele inclusive scan
    for (int off = 1; off < SCAN_THREADS; off <<= 1) {
        int v = (t >= off) ? partial[t - off] : 0;
        __syncthreads();
        if (t >= off) partial[t] += v;
        __syncthreads();
    }
    int run = (t == 0) ? 0 : partial[t - 1];   // exclusive prefix
    for (int i = begin; i < end; i++) {
        int c = g_cnt[i];
        g_off[i] = run;
        g_cursor[i] = run;
        run += c;
    }
    if (t == SCAN_THREADS - 1) g_off[NN] = partial[SCAN_THREADS - 1];
}

// Pass B: compute normalized weight, bucket-scatter packed edge {src, nw}.
__global__ void passB_kernel(const float* __restrict__ ew) {
    int e = blockIdx.x * blockDim.x + threadIdx.x;
    if (e >= EE) return;
    int s = g_src[e];
    int d = g_dst[e];
    float w = (s == d) ? 0.f : ew[e];
    float nw = w * g_deg[s] * g_deg[d];
    int pos = atomicAdd(&g_cursor[d], 1);
    unsigned long long p = (unsigned)s |
        ((unsigned long long)__float_as_uint(nw) << 32);
    g_edges[pos] = p;
}

// Gate kernel: gathers ax = agg(nw*x[src]), ah = agg(nw*H[src]) per node
// (warp-per-node, lane = feature), stores ax for out_kernel reuse, then
// Z = sigmoid(chebZ), R = sigmoid(chebR), HR = H*R. W1 pre-negated in smem.
__global__ void __launch_bounds__(256) gate_kernel(
    const float* __restrict__ x, const float* __restrict__ H,
    const float* __restrict__ Wxz, const float* __restrict__ bxz,
    const float* __restrict__ Whz, const float* __restrict__ bhz,
    const float* __restrict__ Wxr, const float* __restrict__ bxr,
    const float* __restrict__ Whr, const float* __restrict__ bhr) {
    __shared__ float sW[8 * 1024];
    __shared__ float sbz[32];
    __shared__ float sbr[32];

    const float* mats[4] = {Wxz, Whz, Wxr, Whr};
    for (int i = threadIdx.x; i < 8 * 1024; i += blockDim.x) {
        int m = i >> 10;        // [Wxz0,Wxz1, Whz0,Whz1, Wxr0,Wxr1, Whr0,Whr1]
        int r = i & 1023;
        float v = mats[m >> 1][(m & 1) * 1024 + r];
        sW[i] = (m & 1) ? -v : v;   // fold tx1 = -agg into W1
    }
    if (threadIdx.x < 32) {
        sbz[threadIdx.x] = bxz[threadIdx.x] + bhz[threadIdx.x];
        sbr[threadIdx.x] = bxr[threadIdx.x] + bhr[threadIdx.x];
    }
    __syncthreads();

    int node = blockIdx.x * 8 + (threadIdx.x >> 5);
    if (node >= NN) return;
    int lane = threadIdx.x & 31;
    size_t base = (size_t)node * FH + lane;

    // ---- gather phase (no atomics) ----
    int beg = g_off[node];
    int end = g_off[node + 1];
    float ax = 0.f, ah = 0.f;
    for (int j = beg; j < end; j++) {
        unsigned long long p = g_edges[j];
        int s = (int)(unsigned)p;
        float wv = __uint_as_float((unsigned)(p >> 32));
        size_t sb = (size_t)s * FH + lane;
        ax = fmaf(wv, __ldg(x + sb), ax);
        ah = fmaf(wv, __ldg(H + sb), ah);
    }
    g_aggx[base] = ax;

    float xv = x[base];
    float hv = H[base];
    float az = sbz[lane];
    float ar = sbr[lane];

#pragma unroll
    for (int k = 0; k < 32; k++) {
        float xs  = __shfl_sync(0xffffffffu, xv, k);
        float axs = __shfl_sync(0xffffffffu, ax, k);
        float hs  = __shfl_sync(0xffffffffu, hv, k);
        float ahs = __shfl_sync(0xffffffffu, ah, k);
        int o = k * 32 + lane;
        az = fmaf(xs,  sW[o],        az);
        az = fmaf(axs, sW[1024 + o], az);
        az = fmaf(hs,  sW[2048 + o], az);
        az = fmaf(ahs, sW[3072 + o], az);
        ar = fmaf(xs,  sW[4096 + o], ar);
        ar = fmaf(axs, sW[5120 + o], ar);
        ar = fmaf(hs,  sW[6144 + o], ar);
        ar = fmaf(ahs, sW[7168 + o], ar);
    }
    float z = 1.f / (1.f + __expf(-az));
    float r = 1.f / (1.f + __expf(-ar));
    g_Z[base]  = z;
    g_HR[base] = hv * r;
}

// Out kernel: gathers ahr = agg(nw*HR[src]) per node, then
// H_tilde = tanh(chebH), h = Z*H + (1-Z)*H_tilde, out = relu(h)@lin_w + lin_b.
__global__ void __launch_bounds__(256) out_kernel(
    const float* __restrict__ x, const float* __restrict__ H,
    const float* __restrict__ Wxh, const float* __restrict__ bxh,
    const float* __restrict__ Whh, const float* __restrict__ bhh,
    const float* __restrict__ lw, const float* __restrict__ lb,
    float* __restrict__ out, int out_size) {
    __shared__ float sW[4 * 1024];
    __shared__ float sbh[32];
    __shared__ float slw[128];
    __shared__ float slb[4];

    for (int i = threadIdx.x; i < 4 * 1024; i += blockDim.x) {
        int m = i >> 10;        // [Wxh0,Wxh1, Whh0,Whh1]
        int r = i & 1023;
        const float* Wp = (m < 2) ? Wxh : Whh;
        float v = Wp[(m & 1) * 1024 + r];
        sW[i] = (m & 1) ? -v : v;
    }
    if (threadIdx.x < 32) sbh[threadIdx.x] = bxh[threadIdx.x] + bhh[threadIdx.x];
    if (threadIdx.x < 128) slw[threadIdx.x] = lw[threadIdx.x];
    if (threadIdx.x < 4) slb[threadIdx.x] = lb[threadIdx.x];
    __syncthreads();

    int node = blockIdx.x * 8 + (threadIdx.x >> 5);
    if (node >= NN) return;
    int lane = threadIdx.x & 31;
    size_t base = (size_t)node * FH + lane;

    // ---- gather phase on HR ----
    int beg = g_off[node];
    int end = g_off[node + 1];
    float ahr = 0.f;
    for (int j = beg; j < end; j++) {
        unsigned long long p = g_edges[j];
        int s = (int)(unsigned)p;
        float wv = __uint_as_float((unsigned)(p >> 32));
        ahr = fmaf(wv, __ldg(g_HR + (size_t)s * FH + lane), ahr);
    }

    float xv  = x[base];
    float hrv = g_HR[base];
    float ax  = g_aggx[base];
    float a = sbh[lane];

#pragma unroll
    for (int k = 0; k < 32; k++) {
        float xs  = __shfl_sync(0xffffffffu, xv, k);
        float axs = __shfl_sync(0xffffffffu, ax, k);
        float hs  = __shfl_sync(0xffffffffu, hrv, k);
        float ahs = __shfl_sync(0xffffffffu, ahr, k);
        int o = k * 32 + lane;
        a = fmaf(xs,  sW[o],        a);
        a = fmaf(axs, sW[1024 + o], a);
        a = fmaf(hs,  sW[2048 + o], a);
        a = fmaf(ahs, sW[3072 + o], a);
    }
    float ht = tanhf(a);
    float z = g_Z[base];
    float hval = z * H[base] + (1.f - z) * ht;

    long long hidx = (long long)NN * 4 + (long long)base;
    if (hidx < (long long)out_size) out[hidx] = hval;

    float rh = fmaxf(hval, 0.f);
#pragma unroll
    for (int j = 0; j < 4; j++) {
        float s = rh * slw[lane * 4 + j];
#pragma unroll
        for (int off = 16; off; off >>= 1) s += __shfl_xor_sync(0xffffffffu, s, off);
        if (lane == 0 && (long long)node * 4 + j < (long long)out_size)
            out[(size_t)node * 4 + j] = s + slb[j];
    }
}

// ---------------- launch ----------------
extern "C" void kernel_launch(void* const* d_in, const int* in_sizes, int n_in,
                              void* d_out, int out_size) {
    const float* x   = (const float*)d_in[0];
    const void*  ei  = d_in[1];
    const float* ew  = (const float*)d_in[2];
    const float* H   = (const float*)d_in[3];
    const float* Wxz = (const float*)d_in[4];
    const float* bxz = (const float*)d_in[5];
    const float* Whz = (const float*)d_in[6];
    const float* bhz = (const float*)d_in[7];
    const float* Wxr = (const float*)d_in[8];
    const float* bxr = (const float*)d_in[9];
    const float* Whr = (const float*)d_in[10];
    const float* bhr = (const float*)d_in[11];
    const float* Wxh = (const float*)d_in[12];
    const float* bxh = (const float*)d_in[13];
    const float* Whh = (const float*)d_in[14];
    const float* bhh = (const float*)d_in[15];
    const float* lw  = (const float*)d_in[16];
    const float* lb  = (const float*)d_in[17];
    float* out = (float*)d_out;

    detect_kernel<<<1, 1>>>(ei);
    zero_kernel<<<(NN + 255) / 256, 256>>>();
    passA_kernel<<<(EE + 255) / 256, 256>>>(ei, ew);
    dinv_kernel<<<(NN + 255) / 256, 256>>>();
    scan_kernel<<<1, SCAN_THREADS>>>();
    passB_kernel<<<(EE + 255) / 256, 256>>>(ew);
    gate_kernel<<<(NN + 7) / 8, 256>>>(x, H, Wxz, bxz, Whz, bhz, Wxr, bxr, Whr, bhr);
    out_kernel<<<(NN + 7) / 8, 256>>>(x, H, Wxh, bxh, Whh, bhh, lw, lb, out, out_size);
}

// round 5
// speedup vs baseline: 1.0018x; 1.0018x over previous
#include <cuda_runtime.h>

#define NN 100000
#define EE 1600000
#define FH 32
#define SCAN_THREADS 1024
#define BINS_PER_THREAD 98   // 1024*98 = 100352 >= NN

// ---------------- device scratch (static; no allocations) ----------------
__device__ int g_idx64;                          // 1 if edge_index is int64
__device__ __align__(16) int   g_src[EE];
__device__ __align__(16) int   g_dst[EE];
__device__ __align__(16) unsigned long long g_edges[EE];  // packed {src(lo32), nw bits(hi32)}, bucketed by dst
__device__ __align__(16) float g_deg[NN];        // weighted out-degree, then dinv
__device__ __align__(16) int   g_cnt[NN];        // in-degree histogram
__device__ __align__(16) int   g_off[NN + 1];    // CSR offsets (by dst)
__device__ __align__(16) int   g_cursor[NN];     // bucket fill cursors
__device__ __align__(16) float g_aggx[NN * FH];  // agg(nw*x[src]) (stored by gate, reused by out)
__device__ __align__(16) float g_Z[NN * FH];
__device__ __align__(16) float g_HR[NN * FH];

// ---------------- kernels ----------------

// Probe edge_index dtype: true int64 indices are all < NN; int32 data read as
// u64 is >= 2^32 unless the odd word happens to be zero (~1e-5 per entry).
__global__ void detect_kernel(const void* ei) {
    const unsigned long long* p = (const unsigned long long*)ei;
    int is64 = 1;
    for (int i = 0; i < 16; i++)
        if (p[i] >= (unsigned long long)NN) is64 = 0;
    g_idx64 = is64;
}

__global__ void zero_kernel() {
    int i = blockIdx.x * blockDim.x + threadIdx.x;
    if (i < NN) {
        g_deg[i] = 0.f;
        g_cnt[i] = 0;
    }
}

// Pass A: convert indices, weighted out-degree (by src), in-degree histogram (by dst).
__global__ void passA_kernel(const void* ei, const float* __restrict__ ew) {
    int e = blockIdx.x * blockDim.x + threadIdx.x;
    if (e >= EE) return;
    int s, d;
    if (g_idx64) {
        const long long* p = (const long long*)ei;
        s = (int)p[e];
        d = (int)p[EE + e];
    } else {
        const int* p = (const int*)ei;
        s = p[e];
        d = p[EE + e];
    }
    g_src[e] = s;
    g_dst[e] = d;
    float w = (s == d) ? 0.f : ew[e];
    if (w != 0.f) atomicAdd(&g_deg[s], w);
    atomicAdd(&g_cnt[d], 1);
}

__global__ void dinv_kernel() {
    int i = blockIdx.x * blockDim.x + threadIdx.x;
    if (i >= NN) return;
    float dg = g_deg[i];
    g_deg[i] = (dg > 0.f) ? rsqrtf(fmaxf(dg, 1e-30f)) : 0.f;
}

// Single-block exclusive scan of g_cnt -> g_off (+ cursor copy, + g_off[NN]).
__global__ void __launch_bounds__(SCAN_THREADS) scan_kernel() {
    __shared__ int partial[SCAN_THREADS];
    int t = threadIdx.x;
    int begin = t * BINS_PER_THREAD;
    int end = min(begin + BINS_PER_THREAD, NN);
    int sum = 0;
    for (int i = begin; i < end; i++) sum += g_cnt[i];
    partial[t] = sum;
    __syncthreads();
    // Hillis-Steele inclusive scan
    for (int off = 1; off < SCAN_THREADS; off <<= 1) {
        int v = (t >= off) ? partial[t - off] : 0;
        __syncthreads();
        if (t >= off) partial[t] += v;
        __syncthreads();
    }
    int run = (t == 0) ? 0 : partial[t - 1];   // exclusive prefix
    for (int i = begin; i < end; i++) {
        int c = g_cnt[i];
        g_off[i] = run;
        g_cursor[i] = run;
        run += c;
    }
    if (t == SCAN_THREADS - 1) g_off[NN] = partial[SCAN_THREADS - 1];
}

// Pass B: compute normalized weight, bucket-scatter packed edge {src, nw}.
__global__ void passB_kernel(const float* __restrict__ ew) {
    int e = blockIdx.x * blockDim.x + threadIdx.x;
    if (e >= EE) return;
    int s = g_src[e];
    int d = g_dst[e];
    float w = (s == d) ? 0.f : ew[e];
    float nw = w * g_deg[s] * g_deg[d];
    int pos = atomicAdd(&g_cursor[d], 1);
    unsigned long long p = (unsigned)s |
        ((unsigned long long)__float_as_uint(nw) << 32);
    g_edges[pos] = p;
}

// Gate kernel: gathers ax = agg(nw*x[src]), ah = agg(nw*H[src]) per node
// (warp-per-node, lane = feature), stores ax for out_kernel reuse, then
// Z = sigmoid(chebZ), R = sigmoid(chebR), HR = H*R. W1 pre-negated in smem.
__global__ void __launch_bounds__(256) gate_kernel(
    const float* __restrict__ x, const float* __restrict__ H,
    const float* __restrict__ Wxz, const float* __restrict__ bxz,
    const float* __restrict__ Whz, const float* __restrict__ bhz,
    const float* __restrict__ Wxr, const float* __restrict__ bxr,
    const float* __restrict__ Whr, const float* __restrict__ bhr) {
    __shared__ float sW[8 * 1024];
    __shared__ float sbz[32];
    __shared__ float sbr[32];

    const float* mats[4] = {Wxz, Whz, Wxr, Whr};
    for (int i = threadIdx.x; i < 8 * 1024; i += blockDim.x) {
        int m = i >> 10;        // [Wxz0,Wxz1, Whz0,Whz1, Wxr0,Wxr1, Whr0,Whr1]
        int r = i & 1023;
        float v = mats[m >> 1][(m & 1) * 1024 + r];
        sW[i] = (m & 1) ? -v : v;   // fold tx1 = -agg into W1
    }
    if (threadIdx.x < 32) {
        sbz[threadIdx.x] = bxz[threadIdx.x] + bhz[threadIdx.x];
        sbr[threadIdx.x] = bxr[threadIdx.x] + bhr[threadIdx.x];
    }
    __syncthreads();

    int node = blockIdx.x * 8 + (threadIdx.x >> 5);
    if (node >= NN) return;
    int lane = threadIdx.x & 31;
    size_t base = (size_t)node * FH + lane;

    // ---- gather phase (no atomics) ----
    int beg = g_off[node];
    int end = g_off[node + 1];
    float ax = 0.f, ah = 0.f;
    for (int j = beg; j < end; j++) {
        unsigned long long p = g_edges[j];
        int s = (int)(unsigned)p;
        float wv = __uint_as_float((unsigned)(p >> 32));
        size_t sb = (size_t)s * FH + lane;
        ax = fmaf(wv, __ldg(x + sb), ax);
        ah = fmaf(wv, __ldg(H + sb), ah);
    }
    g_aggx[base] = ax;

    float xv = x[base];
    float hv = H[base];
    float az = sbz[lane];
    float ar = sbr[lane];

#pragma unroll
    for (int k = 0; k < 32; k++) {
        float xs  = __shfl_sync(0xffffffffu, xv, k);
        float axs = __shfl_sync(0xffffffffu, ax, k);
        float hs  = __shfl_sync(0xffffffffu, hv, k);
        float ahs = __shfl_sync(0xffffffffu, ah, k);
        int o = k * 32 + lane;
        az = fmaf(xs,  sW[o],        az);
        az = fmaf(axs, sW[1024 + o], az);
        az = fmaf(hs,  sW[2048 + o], az);
        az = fmaf(ahs, sW[3072 + o], az);
        ar = fmaf(xs,  sW[4096 + o], ar);
        ar = fmaf(axs, sW[5120 + o], ar);
        ar = fmaf(hs,  sW[6144 + o], ar);
        ar = fmaf(ahs, sW[7168 + o], ar);
    }
    float z = 1.f / (1.f + __expf(-az));
    float r = 1.f / (1.f + __expf(-ar));
    g_Z[base]  = z;
    g_HR[base] = hv * r;
}

// Out kernel: gathers ahr = agg(nw*HR[src]) per node, then
// H_tilde = tanh(chebH), h = Z*H + (1-Z)*H_tilde, out = relu(h)@lin_w + lin_b.
__global__ void __launch_bounds__(256) out_kernel(
    const float* __restrict__ x, const float* __restrict__ H,
    const float* __restrict__ Wxh, const float* __restrict__ bxh,
    const float* __restrict__ Whh, const float* __restrict__ bhh,
    const float* __restrict__ lw, const float* __restrict__ lb,
    float* __restrict__ out, int out_size) {
    __shared__ float sW[4 * 1024];
    __shared__ float sbh[32];
    __shared__ float slw[128];
    __shared__ float slb[4];

    for (int i = threadIdx.x; i < 4 * 1024; i += blockDim.x) {
        int m = i >> 10;        // [Wxh0,Wxh1, Whh0,Whh1]
        int r = i & 1023;
        const float* Wp = (m < 2) ? Wxh : Whh;
        float v = Wp[(m & 1) * 1024 + r];
        sW[i] = (m & 1) ? -v : v;
    }
    if (threadIdx.x < 32) sbh[threadIdx.x] = bxh[threadIdx.x] + bhh[threadIdx.x];
    if (threadIdx.x < 128) slw[threadIdx.x] = lw[threadIdx.x];
    if (threadIdx.x < 4) slb[threadIdx.x] = lb[threadIdx.x];
    __syncthreads();

    int node = blockIdx.x * 8 + (threadIdx.x >> 5);
    if (node >= NN) return;
    int lane = threadIdx.x & 31;
    size_t base = (size_t)node * FH + lane;

    // ---- gather phase on HR ----
    int beg = g_off[node];
    int end = g_off[node + 1];
    float ahr = 0.f;
    for (int j = beg; j < end; j++) {
        unsigned long long p = g_edges[j];
        int s = (int)(unsigned)p;
        float wv = __uint_as_float((unsigned)(p >> 32));
        ahr = fmaf(wv, __ldg(g_HR + (size_t)s * FH + lane), ahr);
    }

    float xv  = x[base];
    float hrv = g_HR[base];
    float ax  = g_aggx[base];
    float a = sbh[lane];

#pragma unroll
    for (int k = 0; k < 32; k++) {
        float xs  = __shfl_sync(0xffffffffu, xv, k);
        float axs = __shfl_sync(0xffffffffu, ax, k);
        float hs  = __shfl_sync(0xffffffffu, hrv, k);
        float ahs = __shfl_sync(0xffffffffu, ahr, k);
        int o = k * 32 + lane;
        a = fmaf(xs,  sW[o],        a);
        a = fmaf(axs, sW[1024 + o], a);
        a = fmaf(hs,  sW[2048 + o], a);
        a = fmaf(ahs, sW[3072 + o], a);
    }
    float ht = tanhf(a);
    float z = g_Z[base];
    float hval = z * H[base] + (1.f - z) * ht;

    long long hidx = (long long)NN * 4 + (long long)base;
    if (hidx < (long long)out_size) out[hidx] = hval;

    float rh = fmaxf(hval, 0.f);
#pragma unroll
    for (int j = 0; j < 4; j++) {
        float s = rh * slw[lane * 4 + j];
#pragma unroll
        for (int off = 16; off; off >>= 1) s += __shfl_xor_sync(0xffffffffu, s, off);
        if (lane == 0 && (long long)node * 4 + j < (long long)out_size)
            out[(size_t)node * 4 + j] = s + slb[j];
    }
}

// ---------------- launch ----------------
extern "C" void kernel_launch(void* const* d_in, const int* in_sizes, int n_in,
                              void* d_out, int out_size) {
    const float* x   = (const float*)d_in[0];
    const void*  ei  = d_in[1];
    const float* ew  = (const float*)d_in[2];
    const float* H   = (const float*)d_in[3];
    const float* Wxz = (const float*)d_in[4];
    const float* bxz = (const float*)d_in[5];
    const float* Whz = (const float*)d_in[6];
    const float* bhz = (const float*)d_in[7];
    const float* Wxr = (const float*)d_in[8];
    const float* bxr = (const float*)d_in[9];
    const float* Whr = (const float*)d_in[10];
    const float* bhr = (const float*)d_in[11];
    const float* Wxh = (const float*)d_in[12];
    const float* bxh = (const float*)d_in[13];
    const float* Whh = (const float*)d_in[14];
    const float* bhh = (const float*)d_in[15];
    const float* lw  = (const float*)d_in[16];
    const float* lb  = (const float*)d_in[17];
    float* out = (float*)d_out;

    detect_kernel<<<1, 1>>>(ei);
    zero_kernel<<<(NN + 255) / 256, 256>>>();
    passA_kernel<<<(EE + 255) / 256, 256>>>(ei, ew);
    dinv_kernel<<<(NN + 255) / 256, 256>>>();
    scan_kernel<<<1, SCAN_THREADS>>>();
    passB_kernel<<<(EE + 255) / 256, 256>>>(ew);
    gate_kernel<<<(NN + 7) / 8, 256>>>(x, H, Wxz, bxz, Whz, bhz, Wxr, bxr, Whr, bhr);
    out_kernel<<<(NN + 7) / 8, 256>>>(x, H, Wxh, bxh, Whh, bhh, lw, lb, out, out_size);
}